// round 9
// baseline (speedup 1.0000x reference)
#include <cuda_runtime.h>
#include <cuda_bf16.h>
#include <cstdint>

// RAPiD decode:
//   raw:    (nB=64, nA*6=18, nH=128, nW=128) fp32, channel-major
//   out:    (nB, nA*nH*nW, 6) fp32
//
// R9 = R8 (tanh transcendentals + L2 policies + smem transpose staging)
// with the global-store path moved to the TMA engine:
//   loads : per-thread LDG.64 w/ evict_last policy (proven R2 path)
//   stores: block stages 12KB transposed tile in smem, ONE elected
//           cp.async.bulk (smem->gmem, evict_first policy) replaces
//           768 STG.128 wavefronts per block.
// Rationale: L1tex (56%) and DRAM (58%) are co-limiting; TMA stores remove
// the store half of L1 global wavefronts AND their warp issue/latency cost,
// letting loads+DRAM overlap the drain.

namespace {
constexpr int nB = 64;
constexpr int nA = 3;
constexpr int nH = 128;
constexpr int nW = 128;
constexpr int HW = nH * nW;              // 16384 pixels per (b,a) slice
constexpr int WARPS_PER_BLOCK = 8;
constexpr int PIX_PER_WARP = 64;         // 2 per lane
constexpr int PIX_PER_BLOCK = WARPS_PER_BLOCK * PIX_PER_WARP;  // 512
constexpr int BLOCKS_PER_SLICE = HW / PIX_PER_BLOCK;           // 32
constexpr int OUT_TILE_B = PIX_PER_BLOCK * 6 * 4;              // 12288 B
}

// sigmoid(x) = 0.5 + 0.5*tanh(0.5x)  -- one MUFU.TANH
__device__ __forceinline__ float tanh_half(float x) {
    float t;
    asm("tanh.approx.f32 %0, %1;" : "=f"(t) : "f"(x * 0.5f));
    return t;    // = tanh(x/2) = 2*sigmoid(x)-1
}

__device__ __forceinline__ uint64_t mk_policy_evict_last() {
    uint64_t pol;
    asm("createpolicy.fractional.L2::evict_last.b64 %0, 1.0;" : "=l"(pol));
    return pol;
}

__device__ __forceinline__ uint64_t mk_policy_evict_first() {
    uint64_t pol;
    asm("createpolicy.fractional.L2::evict_first.b64 %0, 1.0;" : "=l"(pol));
    return pol;
}

__device__ __forceinline__ float2 ldg_hint(const float* p, uint64_t pol) {
    float2 v;
    asm("ld.global.nc.L2::cache_hint.v2.f32 {%0, %1}, [%2], %3;"
        : "=f"(v.x), "=f"(v.y) : "l"(p), "l"(pol));
    return v;
}

__device__ __forceinline__ uint32_t smem_u32(const void* p) {
    return (uint32_t)__cvta_generic_to_shared(p);
}

__global__ void __launch_bounds__(256)
rapid_decode_kernel(const float* __restrict__ raw,
                    const float* __restrict__ anchors,
                    const int* __restrict__ img_h_p,
                    const int* __restrict__ img_w_p,
                    float* __restrict__ out)
{
    __shared__ alignas(128) float out_stage[PIX_PER_BLOCK * 6];  // 12 KB

    const int tid  = threadIdx.x;

    const int slice   = blockIdx.x >> 5;                     // / BLOCKS_PER_SLICE
    const int blk_in  = blockIdx.x & (BLOCKS_PER_SLICE - 1);
    const int b = slice / nA;
    const int a = slice - b * nA;

    const int hw0 = blk_in * PIX_PER_BLOCK + 2 * tid;        // even
    const int h   = hw0 >> 7;                                // / nW
    const int w0  = hw0 & (nW - 1);

    const uint64_t pol_in  = mk_policy_evict_last();
    const uint64_t pol_out = mk_policy_evict_first();

    const float img_h = img_h_p ? (float)__ldg(img_h_p) : 1024.0f;
    const float img_w = img_w_p ? (float)__ldg(img_w_p) : 1024.0f;
    const float sx  = img_w * (1.0f / (float)nW);
    const float sy  = img_h * (1.0f / (float)nH);
    const float hsx = 0.5f * sx;
    const float hsy = 0.5f * sy;

    const float aw = __ldg(&anchors[a * 2 + 0]);
    const float ah = __ldg(&anchors[a * 2 + 1]);

    // channel base: raw[(b*18 + a*6 + c)*HW + hw0] -- coalesced LDG.64/channel
    const float* base = raw + ((size_t)(b * (nA * 6) + a * 6) * HW + hw0);
    const float2 rx = ldg_hint(base + 0 * HW, pol_in);
    const float2 ry = ldg_hint(base + 1 * HW, pol_in);
    const float2 rw = ldg_hint(base + 2 * HW, pol_in);
    const float2 rh = ldg_hint(base + 3 * HW, pol_in);
    const float2 ra = ldg_hint(base + 4 * HW, pol_in);
    const float2 rc = ldg_hint(base + 5 * HW, pol_in);

    const float cy  = ((float)h + 0.5f) * sy;
    const float cx0 = ((float)w0 + 0.5f) * sx;
    const float cx1 = ((float)w0 + 1.5f) * sx;

    // pixel 0: sigmoid(x) = 0.5 + 0.5*tanh(x/2)
    const float px0 = fmaf(tanh_half(rx.x), hsx, cx0);
    const float py0 = fmaf(tanh_half(ry.x), hsy, cy);
    const float pw0 = __expf(rw.x) * aw;
    const float ph0 = __expf(rh.x) * ah;
    const float pa0 = tanh_half(ra.x) * 180.0f;             // 360*sig-180
    const float pc0 = fmaf(tanh_half(rc.x), 0.5f, 0.5f);
    // pixel 1
    const float px1 = fmaf(tanh_half(rx.y), hsx, cx1);
    const float py1 = fmaf(tanh_half(ry.y), hsy, cy);
    const float pw1 = __expf(rw.y) * aw;
    const float ph1 = __expf(rh.y) * ah;
    const float pa1 = tanh_half(ra.y) * 180.0f;
    const float pc1 = fmaf(tanh_half(rc.y), 0.5f, 0.5f);

    // transpose-stage into block smem tile (pixel order == tid order):
    // 48B/thread stride, conflict-free within each 8-lane phase
    float4* ws = (float4*)out_stage + 3 * tid;
    ws[0] = make_float4(px0, py0, pw0, ph0);
    ws[1] = make_float4(pa0, pc0, px1, py1);
    ws[2] = make_float4(pw1, ph1, pa1, pc1);

    __syncthreads();

    // ONE bulk store for the block's 12KB contiguous output tile
    if (tid == 0) {
        asm volatile("fence.proxy.async.shared::cta;" ::: "memory");
        float* gdst = out + ((size_t)slice * HW + (size_t)blk_in * PIX_PER_BLOCK) * 6;
        asm volatile(
            "cp.async.bulk.global.shared::cta.bulk_group.L2::cache_hint "
            "[%0], [%1], %2, %3;"
            :: "l"(gdst), "r"(smem_u32(out_stage)),
               "r"((uint32_t)OUT_TILE_B), "l"(pol_out)
            : "memory");
        asm volatile("cp.async.bulk.commit_group;" ::: "memory");
        asm volatile("cp.async.bulk.wait_group 0;" ::: "memory");
    }
}

extern "C" void kernel_launch(void* const* d_in, const int* in_sizes, int n_in,
                              void* d_out, int out_size)
{
    const float* raw     = (const float*)d_in[0];
    const float* anchors = (const float*)d_in[1];
    const int* img_h_p   = (n_in > 2) ? (const int*)d_in[2] : nullptr;
    const int* img_w_p   = (n_in > 3) ? (const int*)d_in[3] : nullptr;
    float* out = (float*)d_out;

    const int grid = nB * nA * BLOCKS_PER_SLICE;   // 6144 blocks
    rapid_decode_kernel<<<grid, 256>>>(raw, anchors, img_h_p, img_w_p, out);
}